// round 6
// baseline (speedup 1.0000x reference)
#include <cuda_runtime.h>

#define N_NODES 262144
#define N_EDGES 2097152
#define GRIDW 8
#define NCLUS 64
#define EPSBN 1e-5f

// ---------------- static device scratch ----------------
__device__ unsigned d_count[N_NODES];
__device__ unsigned d_excl[N_NODES];
__device__ unsigned d_offset[N_NODES];
__device__ unsigned d_cursor[N_NODES];
__device__ unsigned d_blockSum[256];
__device__ unsigned d_blockOff[256];
__device__ int      d_sorted_src[N_EDGES + 8];
__device__ float    d_G1f[N_NODES * 16];  // G1 = x*W1_0 + b1 + pos*W1_pos
__device__ float    d_G2f[N_NODES * 32];  // G2 = W2a^T h1 + b2 + pos*W2_pos
__device__ unsigned char d_clus[N_NODES];
__device__ unsigned d_cnt64[NCLUS];
__device__ unsigned d_cur64[NCLUS];
__device__ int      d_perm[N_NODES];      // nodes grouped (binned) by cluster
__device__ unsigned d_pool[NCLUS * 32];   // encoded nonneg-float max (0 = empty)
__device__ int      d_is64;

__device__ __forceinline__ unsigned warp_iscan(unsigned v, int lane) {
#pragma unroll
    for (int d = 1; d < 32; d <<= 1) {
        unsigned n = __shfl_up_sync(0xffffffffu, v, d);
        if (lane >= d) v += n;
    }
    return v;
}

__device__ __forceinline__ int edge_at(const void* ei, int is64, long long idx) {
    if (is64) return (int)((const long long*)ei)[idx];
    return ((const int*)ei)[idx];
}

// ---------------- K0: zero pool + cluster counters + detect edge dtype --------
__global__ void k_zero(const void* __restrict__ ei) {
    int t = blockIdx.x * blockDim.x + threadIdx.x;
    if (t < NCLUS * 32) d_pool[t] = 0u;
    if (t < NCLUS) d_cnt64[t] = 0u;
    if (t == 0) {
        const int* p = (const int*)ei;
        int all_hi_zero = 1;
#pragma unroll
        for (int k = 0; k < 64; k++)
            if (p[2 * k + 1] != 0) all_hi_zero = 0;
        d_is64 = all_hi_zero;
    }
}

// ---------------- K1: per-node init: count=0, G1, cluster id + cluster hist ---
__global__ void __launch_bounds__(256) k_init(
    const float* __restrict__ x, const float* __restrict__ pos,
    const float* __restrict__ W1, const float* __restrict__ b1)
{
    __shared__ unsigned s_h[NCLUS];
    int t = threadIdx.x;
    if (t < NCLUS) s_h[t] = 0u;
    __syncthreads();

    int i = blockIdx.x * blockDim.x + t;   // grid exactly covers N
    d_count[i] = 0u;
    float xv = x[i];
    float px = pos[3 * i], py = pos[3 * i + 1], pz = pos[3 * i + 2];
#pragma unroll
    for (int q = 0; q < 4; q++) {
        float4 g;
        float* gv = (float*)&g;
#pragma unroll
        for (int j = 0; j < 4; j++) {
            int c = q * 4 + j;
            float v = b1[c];
            v = fmaf(xv, W1[c],      v);
            v = fmaf(px, W1[16 + c], v);
            v = fmaf(py, W1[32 + c], v);
            v = fmaf(pz, W1[48 + c], v);
            gv[j] = v;
        }
        ((float4*)d_G1f)[i * 4 + q] = g;
    }
    int gx = (int)floorf(px * 0.0625f);
    int gy = (int)floorf(py * 0.0625f);
    int cl = min(max(gx + gy * GRIDW, 0), NCLUS - 1);
    d_clus[i] = (unsigned char)cl;
    atomicAdd(&s_h[cl], 1u);
    __syncthreads();
    if (t < NCLUS) atomicAdd(&d_cnt64[t], s_h[t]);
}

// ---------------- K2: edge histogram over dst ---------------------------------
__global__ void k_hist(const void* __restrict__ ei) {
    int e = blockIdx.x * blockDim.x + threadIdx.x;
    int is64 = d_is64;
    if (e < N_EDGES) {
        int dst = edge_at(ei, is64, (long long)N_EDGES + e);
        dst = min(max(dst, 0), N_NODES - 1);
        atomicAdd(&d_count[dst], 1u);
    }
}

// ---------------- K3/K4/K5: exclusive scan of d_count -------------------------
__global__ void __launch_bounds__(1024) k_scanA() {
    int t = threadIdx.x, b = blockIdx.x;
    int lane = t & 31, warp = t >> 5;
    int i = b * 1024 + t;
    unsigned v = d_count[i];
    unsigned incl = warp_iscan(v, lane);
    __shared__ unsigned sw[32];
    if (lane == 31) sw[warp] = incl;
    __syncthreads();
    if (warp == 0) {
        unsigned w = sw[lane];
        unsigned wi = warp_iscan(w, lane);
        sw[lane] = wi - w;
    }
    __syncthreads();
    unsigned excl = incl - v + sw[warp];
    d_excl[i] = excl;
    if (t == 1023) d_blockSum[b] = excl + v;
}

__global__ void k_scanB() {
    int t = threadIdx.x;  // 256 threads
    int lane = t & 31, warp = t >> 5;
    unsigned v = d_blockSum[t];
    unsigned incl = warp_iscan(v, lane);
    __shared__ unsigned sw[8];
    if (lane == 31) sw[warp] = incl;
    __syncthreads();
    if (warp == 0 && lane < 8) {
        unsigned w = sw[lane];
        unsigned wi = w;
#pragma unroll
        for (int d = 1; d < 8; d <<= 1) {
            unsigned n = __shfl_up_sync(0xffu, wi, d);
            if (lane >= d) wi += n;
        }
        sw[lane] = wi - w;
    }
    __syncthreads();
    d_blockOff[t] = incl - v + sw[warp];
    if (t == 0) {  // exclusive scan of cluster counts -> cursors
        unsigned run = 0;
        for (int c = 0; c < NCLUS; c++) {
            unsigned cv = d_cnt64[c];
            d_cur64[c] = run;
            run += cv;
        }
    }
}

__global__ void __launch_bounds__(1024) k_scanC() {
    int i = blockIdx.x * 1024 + threadIdx.x;
    unsigned o = d_excl[i] + d_blockOff[blockIdx.x];
    d_offset[i] = o;
    d_cursor[i] = o;
}

// ---------------- K6: scatter edges into CSR; bin nodes by cluster ------------
__global__ void k_scatter(const void* __restrict__ ei) {
    int e = blockIdx.x * blockDim.x + threadIdx.x;
    int is64 = d_is64;
    if (e < N_EDGES) {
        int src = edge_at(ei, is64, e);
        int dst = edge_at(ei, is64, (long long)N_EDGES + e);
        src = min(max(src, 0), N_NODES - 1);
        dst = min(max(dst, 0), N_NODES - 1);
        unsigned p = atomicAdd(&d_cursor[dst], 1u);
        d_sorted_src[p] = src;
    }
    if (e < N_NODES) {
        int cl = d_clus[e];
        unsigned p2 = atomicAdd(&d_cur64[cl], 1u);
        d_perm[p2] = e;
    }
}

// ---------------- K7: layer1 warp-per-node seg-max, BN+ReLU, emit G2 ----------
// lane&15 = channel for the seg-max; full 32 lanes = output channels of G2.
__global__ void __launch_bounds__(256) k_layer1(
    const float* __restrict__ pos,
    const float* __restrict__ W1,
    const float* __restrict__ bn1m, const float* __restrict__ bn1v,
    const float* __restrict__ bn1w, const float* __restrict__ bn1b,
    const float* __restrict__ W2,   const float* __restrict__ b2)
{
    __shared__ float s_w1p[48];       // W1 rows 1..3 (pos part), [3][16]
    __shared__ float s_a[16], s_b[16];
    __shared__ float s_W2a[16 * 32];  // W2 rows 0..15
    __shared__ float s_W2p[96];       // W2 rows 16..18
    __shared__ float s_b2[32];
    int t = threadIdx.x;
    if (t < 48) s_w1p[t] = W1[16 + t];
    if (t < 16) {
        float sc = bn1w[t] * rsqrtf(bn1v[t] + EPSBN);
        s_a[t] = sc;
        s_b[t] = bn1b[t] - bn1m[t] * sc;
    }
    for (int k = t; k < 512; k += 256) s_W2a[k] = W2[k];
    if (t < 96) s_W2p[t] = W2[16 * 32 + t];
    if (t < 32) s_b2[t] = b2[t];
    __syncthreads();

    int lane = t & 31, w = t >> 5;
    int i = blockIdx.x * 8 + w;
    int c = lane & 15;
    int half = lane >> 4;
    unsigned start = d_offset[i], deg = d_count[i];
    const float NEGINF = __int_as_float(0xff800000);
    float acc = NEGINF;

    for (unsigned e = 0; e < deg; e += 4) {
        unsigned i0 = start + min(e + half,     deg - 1u);
        unsigned i1 = start + min(e + 2u + half, deg - 1u);
        int s0 = d_sorted_src[i0];
        int s1 = d_sorted_src[i1];
        float g0 = d_G1f[s0 * 16 + c];
        float g1 = d_G1f[s1 * 16 + c];
        acc = fmaxf(acc, fmaxf(g0, g1));
    }
    acc = fmaxf(acc, __shfl_xor_sync(0xffffffffu, acc, 16));

    float px = pos[3 * i], py = pos[3 * i + 1], pz = pos[3 * i + 2];
    float dterm = px * s_w1p[c] + py * s_w1p[16 + c] + pz * s_w1p[32 + c];
    float agg = (deg == 0u) ? 0.0f : (acc - dterm);
    float h = fmaxf(fmaf(agg, s_a[c], s_b[c]), 0.0f);   // lane k<16 holds h[k]

    // each lane computes G2 output channel = lane
    float v = s_b2[lane];
    v = fmaf(px, s_W2p[lane],      v);
    v = fmaf(py, s_W2p[32 + lane], v);
    v = fmaf(pz, s_W2p[64 + lane], v);
#pragma unroll
    for (int k = 0; k < 16; k++) {
        float hk = __shfl_sync(0xffffffffu, h, k);
        v = fmaf(hk, s_W2a[k * 32 + lane], v);
    }
    d_G2f[i * 32 + lane] = v;   // coalesced 128B store
}

// ---------------- K8: layer2 warp-per-node (cluster-perm order) + fused pool --
// lane = channel. Each warp processes 32 consecutive perm nodes (same cluster
// almost always), keeping a running register max; flush 1 atomic per change.
__global__ void __launch_bounds__(256) k_layer2pool(
    const float* __restrict__ pos,
    const float* __restrict__ W2,
    const float* __restrict__ bn2m, const float* __restrict__ bn2v,
    const float* __restrict__ bn2w, const float* __restrict__ bn2b)
{
    __shared__ float s_w2p[96];
    __shared__ float s_ab[64];
    int t = threadIdx.x;
    if (t < 96) s_w2p[t] = W2[16 * 32 + t];
    if (t < 32) {
        float sc = bn2w[t] * rsqrtf(bn2v[t] + EPSBN);
        s_ab[t] = sc;
        s_ab[32 + t] = bn2b[t] - bn2m[t] * sc;
    }
    __syncthreads();

    int lane = t & 31, w = t >> 5;
    int gw = blockIdx.x * 8 + w;          // global warp id, 8192 warps
    float wx = s_w2p[lane], wy = s_w2p[32 + lane], wz = s_w2p[64 + lane];
    float sa = s_ab[lane], sb = s_ab[32 + lane];
    const float NEGINF = __int_as_float(0xff800000);

    float run = 0.0f;
    int runcl = -1;
    int base = gw * 32;

    for (int k = 0; k < 32; k++) {
        int i = d_perm[base + k];
        unsigned start = d_offset[i], deg = d_count[i];
        float acc = NEGINF;
        for (unsigned e = 0; e < deg; e += 4) {
            int s0 = d_sorted_src[start + min(e,      deg - 1u)];
            int s1 = d_sorted_src[start + min(e + 1u, deg - 1u)];
            int s2 = d_sorted_src[start + min(e + 2u, deg - 1u)];
            int s3 = d_sorted_src[start + min(e + 3u, deg - 1u)];
            float g0 = d_G2f[s0 * 32 + lane];
            float g1 = d_G2f[s1 * 32 + lane];
            float g2 = d_G2f[s2 * 32 + lane];
            float g3 = d_G2f[s3 * 32 + lane];
            acc = fmaxf(fmaxf(fmaxf(acc, g0), fmaxf(g1, g2)), g3);
        }
        float px = pos[3 * i], py = pos[3 * i + 1], pz = pos[3 * i + 2];
        float agg = (deg == 0u) ? 0.0f : (acc - (px * wx + py * wy + pz * wz));
        float h2 = fmaxf(fmaf(agg, sa, sb), 0.0f);   // >= 0
        int cl = d_clus[i];
        if (cl != runcl) {
            if (runcl >= 0)
                atomicMax(&d_pool[runcl * 32 + lane], __float_as_uint(run) | 0x80000000u);
            runcl = cl;
            run = h2;
        } else {
            run = fmaxf(run, h2);
        }
    }
    if (runcl >= 0)
        atomicMax(&d_pool[runcl * 32 + lane], __float_as_uint(run) | 0x80000000u);
}

// ---------------- K9: decode pooled -> output ---------------------------------
__global__ void k_out(float* __restrict__ out) {
    int t = blockIdx.x * blockDim.x + threadIdx.x;
    if (t < NCLUS * 32) {
        unsigned u = d_pool[t];
        out[t] = u ? __uint_as_float(u & 0x7FFFFFFFu) : 0.0f;
    }
}

// ---------------- host launch -------------------------------------------------
extern "C" void kernel_launch(void* const* d_in, const int* in_sizes, int n_in,
                              void* d_out, int out_size)
{
    const float* x    = (const float*)d_in[0];
    const float* pos  = (const float*)d_in[1];
    const void*  ei   = (const void*)d_in[2];
    const float* W1   = (const float*)d_in[3];
    const float* b1   = (const float*)d_in[4];
    const float* bn1m = (const float*)d_in[5];
    const float* bn1v = (const float*)d_in[6];
    const float* bn1w = (const float*)d_in[7];
    const float* bn1b = (const float*)d_in[8];
    const float* W2   = (const float*)d_in[9];
    const float* b2   = (const float*)d_in[10];
    const float* bn2m = (const float*)d_in[11];
    const float* bn2v = (const float*)d_in[12];
    const float* bn2w = (const float*)d_in[13];
    const float* bn2b = (const float*)d_in[14];
    float* out = (float*)d_out;

    k_zero<<<8, 256>>>(ei);
    k_init<<<N_NODES / 256, 256>>>(x, pos, W1, b1);
    k_hist<<<N_EDGES / 256, 256>>>(ei);
    k_scanA<<<256, 1024>>>();
    k_scanB<<<1, 256>>>();
    k_scanC<<<256, 1024>>>();
    k_scatter<<<N_EDGES / 256, 256>>>(ei);
    k_layer1<<<N_NODES / 8, 256>>>(pos, W1, bn1m, bn1v, bn1w, bn1b, W2, b2);
    k_layer2pool<<<N_NODES / 256, 256>>>(pos, W2, bn2m, bn2v, bn2w, bn2b);
    k_out<<<8, 256>>>(out);
}

// round 9
// speedup vs baseline: 1.9427x; 1.9427x over previous
#include <cuda_runtime.h>
#include <cuda_fp16.h>

#define N_NODES 262144
#define N_EDGES 2097152
#define GRIDW 8
#define NCLUS 64
#define EPSBN 1e-5f

// ---------------- static device scratch ----------------
__device__ unsigned d_count[N_NODES];
__device__ unsigned d_excl[N_NODES];
__device__ unsigned d_offset[N_NODES];
__device__ unsigned d_cursor[N_NODES];
__device__ unsigned d_blockSum[256];
__device__ unsigned d_blockOff[256];
__device__ int      d_sorted_src[N_EDGES + 8];
__device__ uint4    d_G1h[N_NODES * 2];   // fp16: G1 = x*W1_0 + b1 + pos*W1pos [N,16]
__device__ uint4    d_G2h[N_NODES * 4];   // fp16: G2 = W2a^T h1 + b2 + pos*W2pos [N,32]
__device__ unsigned char d_clus[N_NODES];
__device__ unsigned d_pool[NCLUS * 32];   // encoded nonneg-float max (0 = empty)
__device__ int      d_is64;

__device__ __forceinline__ unsigned warp_iscan(unsigned v, int lane) {
#pragma unroll
    for (int d = 1; d < 32; d <<= 1) {
        unsigned n = __shfl_up_sync(0xffffffffu, v, d);
        if (lane >= d) v += n;
    }
    return v;
}

__device__ __forceinline__ int edge_at(const void* ei, int is64, long long idx) {
    if (is64) return (int)((const long long*)ei)[idx];
    return ((const int*)ei)[idx];
}

__device__ __forceinline__ unsigned pack2(float a, float b) {
    __half2 h = __floats2half2_rn(a, b);
    return *reinterpret_cast<unsigned*>(&h);
}
__device__ __forceinline__ __half2 h2max(__half2 a, unsigned b) {
    return __hmax2(a, *reinterpret_cast<__half2*>(&b));
}

// ---------------- K0: zero pool + detect edge dtype ---------------------------
__global__ void k_zero(const void* __restrict__ ei) {
    int t = blockIdx.x * blockDim.x + threadIdx.x;
    if (t < NCLUS * 32) d_pool[t] = 0u;
    if (t == 0) {
        const int* p = (const int*)ei;
        int all_hi_zero = 1;
#pragma unroll
        for (int k = 0; k < 64; k++)
            if (p[2 * k + 1] != 0) all_hi_zero = 0;
        d_is64 = all_hi_zero;
    }
}

// ---------------- K1: per-node init: count=0, G1(fp16), cluster id ------------
__global__ void __launch_bounds__(256) k_init(
    const float* __restrict__ x, const float* __restrict__ pos,
    const float* __restrict__ W1, const float* __restrict__ b1)
{
    int t = threadIdx.x;
    int i = blockIdx.x * blockDim.x + t;   // grid exactly covers N
    d_count[i] = 0u;
    float xv = x[i];
    float px = pos[3 * i], py = pos[3 * i + 1], pz = pos[3 * i + 2];
    float g[16];
#pragma unroll
    for (int c = 0; c < 16; c++) {
        float v = b1[c];
        v = fmaf(xv, W1[c],      v);
        v = fmaf(px, W1[16 + c], v);
        v = fmaf(py, W1[32 + c], v);
        v = fmaf(pz, W1[48 + c], v);
        g[c] = v;
    }
    uint4 u0, u1;
    u0.x = pack2(g[0],  g[1]);  u0.y = pack2(g[2],  g[3]);
    u0.z = pack2(g[4],  g[5]);  u0.w = pack2(g[6],  g[7]);
    u1.x = pack2(g[8],  g[9]);  u1.y = pack2(g[10], g[11]);
    u1.z = pack2(g[12], g[13]); u1.w = pack2(g[14], g[15]);
    d_G1h[i * 2 + 0] = u0;
    d_G1h[i * 2 + 1] = u1;

    int gx = (int)floorf(px * 0.0625f);
    int gy = (int)floorf(py * 0.0625f);
    int cl = min(max(gx + gy * GRIDW, 0), NCLUS - 1);
    d_clus[i] = (unsigned char)cl;
}

// ---------------- K2: edge histogram over dst ---------------------------------
__global__ void k_hist(const void* __restrict__ ei) {
    int e = blockIdx.x * blockDim.x + threadIdx.x;
    int is64 = d_is64;
    if (e < N_EDGES) {
        int dst = edge_at(ei, is64, (long long)N_EDGES + e);
        dst = min(max(dst, 0), N_NODES - 1);
        atomicAdd(&d_count[dst], 1u);
    }
}

// ---------------- K3/K4/K5: exclusive scan of d_count -------------------------
__global__ void __launch_bounds__(1024) k_scanA() {
    int t = threadIdx.x, b = blockIdx.x;
    int lane = t & 31, warp = t >> 5;
    int i = b * 1024 + t;
    unsigned v = d_count[i];
    unsigned incl = warp_iscan(v, lane);
    __shared__ unsigned sw[32];
    if (lane == 31) sw[warp] = incl;
    __syncthreads();
    if (warp == 0) {
        unsigned w = sw[lane];
        unsigned wi = warp_iscan(w, lane);
        sw[lane] = wi - w;
    }
    __syncthreads();
    unsigned excl = incl - v + sw[warp];
    d_excl[i] = excl;
    if (t == 1023) d_blockSum[b] = excl + v;
}

__global__ void k_scanB() {
    int t = threadIdx.x;  // 256 threads
    int lane = t & 31, warp = t >> 5;
    unsigned v = d_blockSum[t];
    unsigned incl = warp_iscan(v, lane);
    __shared__ unsigned sw[8];
    if (lane == 31) sw[warp] = incl;
    __syncthreads();
    if (warp == 0 && lane < 8) {
        unsigned w = sw[lane];
        unsigned wi = w;
#pragma unroll
        for (int d = 1; d < 8; d <<= 1) {
            unsigned n = __shfl_up_sync(0xffu, wi, d);
            if (lane >= d) wi += n;
        }
        sw[lane] = wi - w;
    }
    __syncthreads();
    d_blockOff[t] = incl - v + sw[warp];
}

__global__ void __launch_bounds__(1024) k_scanC() {
    int i = blockIdx.x * 1024 + threadIdx.x;
    unsigned o = d_excl[i] + d_blockOff[blockIdx.x];
    d_offset[i] = o;
    d_cursor[i] = o;
}

// ---------------- K6: scatter edges into CSR ----------------------------------
__global__ void k_scatter(const void* __restrict__ ei) {
    int e = blockIdx.x * blockDim.x + threadIdx.x;
    int is64 = d_is64;
    if (e < N_EDGES) {
        int src = edge_at(ei, is64, e);
        int dst = edge_at(ei, is64, (long long)N_EDGES + e);
        src = min(max(src, 0), N_NODES - 1);
        dst = min(max(dst, 0), N_NODES - 1);
        unsigned p = atomicAdd(&d_cursor[dst], 1u);
        d_sorted_src[p] = src;
    }
}

// ---------------- K7: layer1 thread-per-node seg-max(fp16), BN+ReLU, emit G2 --
__global__ void __launch_bounds__(256) k_layer1(
    const float* __restrict__ pos,
    const float* __restrict__ W1,
    const float* __restrict__ bn1m, const float* __restrict__ bn1v,
    const float* __restrict__ bn1w, const float* __restrict__ bn1b,
    const float* __restrict__ W2,   const float* __restrict__ b2)
{
    __shared__ float s_w1p[48];       // W1 rows 1..3 (pos part)
    __shared__ float s_a[16], s_b[16];
    __shared__ float s_W2a[16 * 32];  // W2 rows 0..15
    __shared__ float s_W2p[96];       // W2 rows 16..18
    __shared__ float s_b2[32];
    int t = threadIdx.x;
    if (t < 48) s_w1p[t] = W1[16 + t];
    if (t < 16) {
        float sc = bn1w[t] * rsqrtf(bn1v[t] + EPSBN);
        s_a[t] = sc;
        s_b[t] = bn1b[t] - bn1m[t] * sc;
    }
    for (int k = t; k < 512; k += 256) s_W2a[k] = W2[k];
    if (t < 96) s_W2p[t] = W2[16 * 32 + t];
    if (t < 32) s_b2[t] = b2[t];
    __syncthreads();

    int i = blockIdx.x * blockDim.x + t;
    unsigned start = d_offset[i], deg = d_count[i];
    const __half2 NEGINF2 = __floats2half2_rn(-65504.0f, -65504.0f);
    __half2 acc[8];
#pragma unroll
    for (int q = 0; q < 8; q++) acc[q] = NEGINF2;

#pragma unroll 2
    for (unsigned e = 0; e < deg; e++) {
        int s = d_sorted_src[start + e];
        uint4 u0 = d_G1h[s * 2 + 0];
        uint4 u1 = d_G1h[s * 2 + 1];
        acc[0] = h2max(acc[0], u0.x); acc[1] = h2max(acc[1], u0.y);
        acc[2] = h2max(acc[2], u0.z); acc[3] = h2max(acc[3], u0.w);
        acc[4] = h2max(acc[4], u1.x); acc[5] = h2max(acc[5], u1.y);
        acc[6] = h2max(acc[6], u1.z); acc[7] = h2max(acc[7], u1.w);
    }
    float accf[16];
#pragma unroll
    for (int q = 0; q < 8; q++) {
        float2 f = __half22float2(acc[q]);
        accf[2 * q] = f.x; accf[2 * q + 1] = f.y;
    }

    float px = pos[3 * i], py = pos[3 * i + 1], pz = pos[3 * i + 2];
    float h[16];
#pragma unroll
    for (int c = 0; c < 16; c++) {
        float dterm = px * s_w1p[c] + py * s_w1p[16 + c] + pz * s_w1p[32 + c];
        float agg = (deg == 0u) ? 0.0f : (accf[c] - dterm);
        h[c] = fmaxf(fmaf(agg, s_a[c], s_b[c]), 0.0f);
    }
    // G2 = W2a^T h + b2 + pos*W2pos  (fp32), then pack fp16
    float g2a[32];
#pragma unroll
    for (int c = 0; c < 32; c++) {
        float v = s_b2[c];
        v = fmaf(px, s_W2p[c],      v);
        v = fmaf(py, s_W2p[32 + c], v);
        v = fmaf(pz, s_W2p[64 + c], v);
        g2a[c] = v;
    }
#pragma unroll
    for (int k = 0; k < 16; k++) {
        float hk = h[k];
#pragma unroll
        for (int c = 0; c < 32; c++) g2a[c] = fmaf(hk, s_W2a[k * 32 + c], g2a[c]);
    }
#pragma unroll
    for (int q = 0; q < 4; q++) {
        uint4 u;
        u.x = pack2(g2a[8 * q + 0], g2a[8 * q + 1]);
        u.y = pack2(g2a[8 * q + 2], g2a[8 * q + 3]);
        u.z = pack2(g2a[8 * q + 4], g2a[8 * q + 5]);
        u.w = pack2(g2a[8 * q + 6], g2a[8 * q + 7]);
        d_G2h[i * 4 + q] = u;
    }
}

// ---------------- K8: layer2 thread-per-node seg-max(fp16), BN+ReLU, pool -----
__global__ void __launch_bounds__(256) k_layer2pool(
    const float* __restrict__ pos,
    const float* __restrict__ W2,
    const float* __restrict__ bn2m, const float* __restrict__ bn2v,
    const float* __restrict__ bn2w, const float* __restrict__ bn2b)
{
    __shared__ float s_w2p[96];   // W2 rows 16..18
    __shared__ float s_a[32], s_b[32];
    __shared__ unsigned s_pool[NCLUS * 32];
    int t = threadIdx.x;
    if (t < 96) s_w2p[t] = W2[16 * 32 + t];
    if (t < 32) {
        float sc = bn2w[t] * rsqrtf(bn2v[t] + EPSBN);
        s_a[t] = sc;
        s_b[t] = bn2b[t] - bn2m[t] * sc;
    }
#pragma unroll
    for (int q = 0; q < 8; q++) s_pool[q * 256 + t] = 0u;
    __syncthreads();

    int i = blockIdx.x * blockDim.x + t;
    unsigned start = d_offset[i], deg = d_count[i];
    const __half2 NEGINF2 = __floats2half2_rn(-65504.0f, -65504.0f);
    __half2 acc[16];
#pragma unroll
    for (int q = 0; q < 16; q++) acc[q] = NEGINF2;

#pragma unroll 2
    for (unsigned e = 0; e < deg; e++) {
        int s = d_sorted_src[start + e];
        uint4 u0 = d_G2h[s * 4 + 0];
        uint4 u1 = d_G2h[s * 4 + 1];
        uint4 u2 = d_G2h[s * 4 + 2];
        uint4 u3 = d_G2h[s * 4 + 3];
        acc[0]  = h2max(acc[0],  u0.x); acc[1]  = h2max(acc[1],  u0.y);
        acc[2]  = h2max(acc[2],  u0.z); acc[3]  = h2max(acc[3],  u0.w);
        acc[4]  = h2max(acc[4],  u1.x); acc[5]  = h2max(acc[5],  u1.y);
        acc[6]  = h2max(acc[6],  u1.z); acc[7]  = h2max(acc[7],  u1.w);
        acc[8]  = h2max(acc[8],  u2.x); acc[9]  = h2max(acc[9],  u2.y);
        acc[10] = h2max(acc[10], u2.z); acc[11] = h2max(acc[11], u2.w);
        acc[12] = h2max(acc[12], u3.x); acc[13] = h2max(acc[13], u3.y);
        acc[14] = h2max(acc[14], u3.z); acc[15] = h2max(acc[15], u3.w);
    }

    float px = pos[3 * i], py = pos[3 * i + 1], pz = pos[3 * i + 2];
    int cl = d_clus[i];
    unsigned base = (unsigned)cl * 32u;
#pragma unroll
    for (int q = 0; q < 16; q++) {
        float2 f = __half22float2(acc[q]);
#pragma unroll
        for (int j = 0; j < 2; j++) {
            int c = 2 * q + j;
            float av = j ? f.y : f.x;
            float dterm = px * s_w2p[c] + py * s_w2p[32 + c] + pz * s_w2p[64 + c];
            float agg = (deg == 0u) ? 0.0f : (av - dterm);
            float h2v = fmaxf(fmaf(agg, s_a[c], s_b[c]), 0.0f);   // >= 0
            atomicMax(&s_pool[base + c], __float_as_uint(h2v) | 0x80000000u);
        }
    }
    __syncthreads();
#pragma unroll
    for (int q = 0; q < 8; q++) {
        int j = q * 256 + t;
        unsigned v = s_pool[j];
        if (v) atomicMax(&d_pool[j], v);
    }
}

// ---------------- K9: decode pooled -> output ---------------------------------
__global__ void k_out(float* __restrict__ out) {
    int t = blockIdx.x * blockDim.x + threadIdx.x;
    if (t < NCLUS * 32) {
        unsigned u = d_pool[t];
        out[t] = u ? __uint_as_float(u & 0x7FFFFFFFu) : 0.0f;
    }
}

// ---------------- host launch -------------------------------------------------
extern "C" void kernel_launch(void* const* d_in, const int* in_sizes, int n_in,
                              void* d_out, int out_size)
{
    const float* x    = (const float*)d_in[0];
    const float* pos  = (const float*)d_in[1];
    const void*  ei   = (const void*)d_in[2];
    const float* W1   = (const float*)d_in[3];
    const float* b1   = (const float*)d_in[4];
    const float* bn1m = (const float*)d_in[5];
    const float* bn1v = (const float*)d_in[6];
    const float* bn1w = (const float*)d_in[7];
    const float* bn1b = (const float*)d_in[8];
    const float* W2   = (const float*)d_in[9];
    const float* b2   = (const float*)d_in[10];
    const float* bn2m = (const float*)d_in[11];
    const float* bn2v = (const float*)d_in[12];
    const float* bn2w = (const float*)d_in[13];
    const float* bn2b = (const float*)d_in[14];
    float* out = (float*)d_out;

    k_zero<<<8, 256>>>(ei);
    k_init<<<N_NODES / 256, 256>>>(x, pos, W1, b1);
    k_hist<<<N_EDGES / 256, 256>>>(ei);
    k_scanA<<<256, 1024>>>();
    k_scanB<<<1, 256>>>();
    k_scanC<<<256, 1024>>>();
    k_scatter<<<N_EDGES / 256, 256>>>(ei);
    k_layer1<<<N_NODES / 256, 256>>>(pos, W1, bn1m, bn1v, bn1w, bn1b, W2, b2);
    k_layer2pool<<<N_NODES / 256, 256>>>(pos, W2, bn2m, bn2v, bn2w, bn2b);
    k_out<<<8, 256>>>(out);
}

// round 10
// speedup vs baseline: 2.4557x; 1.2641x over previous
#include <cuda_runtime.h>
#include <cuda_fp16.h>

#define N_NODES 262144
#define N_EDGES 2097152
#define GRIDW 8
#define NCLUS 64
#define EPSBN 1e-5f

// ---------------- static device scratch ----------------
__device__ unsigned d_count[N_NODES];
__device__ unsigned d_excl[N_NODES];
__device__ unsigned d_offset[N_NODES];
__device__ unsigned d_cursor[N_NODES];
__device__ unsigned d_blockSum[256];
__device__ unsigned d_blockOff[256];
__device__ int      d_sorted_src[N_EDGES + 8];
__device__ uint4    d_G1h[N_NODES * 2];   // fp16: G1 = x*W1_0 + b1 + pos*W1pos [N,16]
__device__ uint4    d_G2h[N_NODES * 4];   // fp16: G2 = W2a^T h1 + b2 + pos*W2pos [N,32]
__device__ unsigned char d_clus[N_NODES];
__device__ unsigned d_pool[NCLUS * 32];   // encoded nonneg-float max (0 = empty)
__device__ int      d_is64;

__device__ __forceinline__ unsigned warp_iscan(unsigned v, int lane) {
#pragma unroll
    for (int d = 1; d < 32; d <<= 1) {
        unsigned n = __shfl_up_sync(0xffffffffu, v, d);
        if (lane >= d) v += n;
    }
    return v;
}

__device__ __forceinline__ unsigned pack2(float a, float b) {
    __half2 h = __floats2half2_rn(a, b);
    return *reinterpret_cast<unsigned*>(&h);
}
__device__ __forceinline__ __half2 h2max(__half2 a, unsigned b) {
    return __hmax2(a, *reinterpret_cast<__half2*>(&b));
}

// ---------------- K0: zero pool + detect edge dtype ---------------------------
__global__ void k_zero(const void* __restrict__ ei) {
    int t = blockIdx.x * blockDim.x + threadIdx.x;
    if (t < NCLUS * 32) d_pool[t] = 0u;
    if (t == 0) {
        const int* p = (const int*)ei;
        int all_hi_zero = 1;
#pragma unroll
        for (int k = 0; k < 64; k++)
            if (p[2 * k + 1] != 0) all_hi_zero = 0;
        d_is64 = all_hi_zero;
    }
}

// ---------------- K1: per-node init: count=0, G1(fp16), cluster id ------------
__global__ void __launch_bounds__(256) k_init(
    const float* __restrict__ x, const float* __restrict__ pos,
    const float* __restrict__ W1, const float* __restrict__ b1)
{
    int t = threadIdx.x;
    int i = blockIdx.x * blockDim.x + t;   // grid exactly covers N
    d_count[i] = 0u;
    float xv = x[i];
    float px = pos[3 * i], py = pos[3 * i + 1], pz = pos[3 * i + 2];
    float g[16];
#pragma unroll
    for (int c = 0; c < 16; c++) {
        float v = b1[c];
        v = fmaf(xv, W1[c],      v);
        v = fmaf(px, W1[16 + c], v);
        v = fmaf(py, W1[32 + c], v);
        v = fmaf(pz, W1[48 + c], v);
        g[c] = v;
    }
    uint4 u0, u1;
    u0.x = pack2(g[0],  g[1]);  u0.y = pack2(g[2],  g[3]);
    u0.z = pack2(g[4],  g[5]);  u0.w = pack2(g[6],  g[7]);
    u1.x = pack2(g[8],  g[9]);  u1.y = pack2(g[10], g[11]);
    u1.z = pack2(g[12], g[13]); u1.w = pack2(g[14], g[15]);
    d_G1h[i * 2 + 0] = u0;
    d_G1h[i * 2 + 1] = u1;

    int gx = (int)floorf(px * 0.0625f);
    int gy = (int)floorf(py * 0.0625f);
    int cl = min(max(gx + gy * GRIDW, 0), NCLUS - 1);
    d_clus[i] = (unsigned char)cl;
}

// ---------------- K2: edge histogram over dst (2 edges/thread) ----------------
__global__ void k_hist(const void* __restrict__ ei) {
    int g = blockIdx.x * blockDim.x + threadIdx.x;   // E/2 threads
    int is64 = d_is64;
    int d0, d1;
    if (is64) {
        longlong2 v = ((const longlong2*)ei)[N_EDGES / 2 + g];
        d0 = (int)v.x; d1 = (int)v.y;
    } else {
        int2 v = ((const int2*)((const int*)ei + N_EDGES))[g];
        d0 = v.x; d1 = v.y;
    }
    d0 = min(max(d0, 0), N_NODES - 1);
    d1 = min(max(d1, 0), N_NODES - 1);
    atomicAdd(&d_count[d0], 1u);
    atomicAdd(&d_count[d1], 1u);
}

// ---------------- K3/K4/K5: exclusive scan of d_count -------------------------
__global__ void __launch_bounds__(1024) k_scanA() {
    int t = threadIdx.x, b = blockIdx.x;
    int lane = t & 31, warp = t >> 5;
    int i = b * 1024 + t;
    unsigned v = d_count[i];
    unsigned incl = warp_iscan(v, lane);
    __shared__ unsigned sw[32];
    if (lane == 31) sw[warp] = incl;
    __syncthreads();
    if (warp == 0) {
        unsigned w = sw[lane];
        unsigned wi = warp_iscan(w, lane);
        sw[lane] = wi - w;
    }
    __syncthreads();
    unsigned excl = incl - v + sw[warp];
    d_excl[i] = excl;
    if (t == 1023) d_blockSum[b] = excl + v;
}

__global__ void k_scanB() {
    int t = threadIdx.x;  // 256 threads
    int lane = t & 31, warp = t >> 5;
    unsigned v = d_blockSum[t];
    unsigned incl = warp_iscan(v, lane);
    __shared__ unsigned sw[8];
    if (lane == 31) sw[warp] = incl;
    __syncthreads();
    if (warp == 0 && lane < 8) {
        unsigned w = sw[lane];
        unsigned wi = w;
#pragma unroll
        for (int d = 1; d < 8; d <<= 1) {
            unsigned n = __shfl_up_sync(0xffu, wi, d);
            if (lane >= d) wi += n;
        }
        sw[lane] = wi - w;
    }
    __syncthreads();
    d_blockOff[t] = incl - v + sw[warp];
}

__global__ void __launch_bounds__(1024) k_scanC() {
    int i = blockIdx.x * 1024 + threadIdx.x;
    unsigned o = d_excl[i] + d_blockOff[blockIdx.x];
    d_offset[i] = o;
    d_cursor[i] = o;
}

// ---------------- K6: scatter edges into CSR (2 edges/thread) -----------------
__global__ void k_scatter(const void* __restrict__ ei) {
    int g = blockIdx.x * blockDim.x + threadIdx.x;   // E/2 threads
    int is64 = d_is64;
    int s0, s1, d0, d1;
    if (is64) {
        longlong2 sv = ((const longlong2*)ei)[g];
        longlong2 dv = ((const longlong2*)ei)[N_EDGES / 2 + g];
        s0 = (int)sv.x; s1 = (int)sv.y; d0 = (int)dv.x; d1 = (int)dv.y;
    } else {
        int2 sv = ((const int2*)ei)[g];
        int2 dv = ((const int2*)((const int*)ei + N_EDGES))[g];
        s0 = sv.x; s1 = sv.y; d0 = dv.x; d1 = dv.y;
    }
    s0 = min(max(s0, 0), N_NODES - 1);
    s1 = min(max(s1, 0), N_NODES - 1);
    d0 = min(max(d0, 0), N_NODES - 1);
    d1 = min(max(d1, 0), N_NODES - 1);
    unsigned p0 = atomicAdd(&d_cursor[d0], 1u);
    d_sorted_src[p0] = s0;
    unsigned p1 = atomicAdd(&d_cursor[d1], 1u);
    d_sorted_src[p1] = s1;
}

// ---------------- K7: layer1 pair-per-node seg-max(fp16), BN+ReLU, emit G2 ----
// 2 threads per node; thread half owns channels [half*8, half*8+8).
__global__ void __launch_bounds__(256) k_layer1(
    const float* __restrict__ pos,
    const float* __restrict__ W1,
    const float* __restrict__ bn1m, const float* __restrict__ bn1v,
    const float* __restrict__ bn1w, const float* __restrict__ bn1b,
    const float* __restrict__ W2,   const float* __restrict__ b2)
{
    __shared__ float s_w1p[48];       // W1 rows 1..3 (pos part)
    __shared__ float s_a[16], s_b[16];
    __shared__ float s_W2a[16 * 32];  // W2 rows 0..15
    __shared__ float s_W2p[96];       // W2 rows 16..18
    __shared__ float s_b2[32];
    int t = threadIdx.x;
    if (t < 48) s_w1p[t] = W1[16 + t];
    if (t < 16) {
        float sc = bn1w[t] * rsqrtf(bn1v[t] + EPSBN);
        s_a[t] = sc;
        s_b[t] = bn1b[t] - bn1m[t] * sc;
    }
    for (int k = t; k < 512; k += 256) s_W2a[k] = W2[k];
    if (t < 96) s_W2p[t] = W2[16 * 32 + t];
    if (t < 32) s_b2[t] = b2[t];
    __syncthreads();

    int gid = blockIdx.x * blockDim.x + t;   // 2*N threads
    int i = gid >> 1, half = gid & 1;
    unsigned start = d_offset[i], deg = d_count[i];
    const __half2 NEGINF2 = __floats2half2_rn(-65504.0f, -65504.0f);
    __half2 acc0 = NEGINF2, acc1 = NEGINF2, acc2 = NEGINF2, acc3 = NEGINF2;

#pragma unroll 4
    for (unsigned e = 0; e < deg; e++) {
        int s = d_sorted_src[start + e];
        uint4 u = d_G1h[s * 2 + half];
        acc0 = h2max(acc0, u.x); acc1 = h2max(acc1, u.y);
        acc2 = h2max(acc2, u.z); acc3 = h2max(acc3, u.w);
    }
    float accf[8];
    {
        float2 f0 = __half22float2(acc0), f1 = __half22float2(acc1);
        float2 f2 = __half22float2(acc2), f3 = __half22float2(acc3);
        accf[0] = f0.x; accf[1] = f0.y; accf[2] = f1.x; accf[3] = f1.y;
        accf[4] = f2.x; accf[5] = f2.y; accf[6] = f3.x; accf[7] = f3.y;
    }

    float px = pos[3 * i], py = pos[3 * i + 1], pz = pos[3 * i + 2];
    int c0 = half * 8;
    float h[8];
#pragma unroll
    for (int j = 0; j < 8; j++) {
        int c = c0 + j;
        float dterm = px * s_w1p[c] + py * s_w1p[16 + c] + pz * s_w1p[32 + c];
        float agg = (deg == 0u) ? 0.0f : (accf[j] - dterm);
        h[j] = fmaxf(fmaf(agg, s_a[c], s_b[c]), 0.0f);
    }
    // exchange 8 h values with partner to build full h[16]
    float oth[8];
#pragma unroll
    for (int j = 0; j < 8; j++) oth[j] = __shfl_xor_sync(0xffffffffu, h[j], 1);
    float hl[16];
#pragma unroll
    for (int j = 0; j < 8; j++) {
        hl[c0 + j] = h[j];
        hl[(c0 ^ 8) + j] = oth[j];
    }
    // this thread computes G2 output channels [half*16, half*16+16)
    int cc0 = half * 16;
    float g2a[16];
#pragma unroll
    for (int k = 0; k < 16; k++) {
        int cc = cc0 + k;
        float v = s_b2[cc];
        v = fmaf(px, s_W2p[cc],      v);
        v = fmaf(py, s_W2p[32 + cc], v);
        v = fmaf(pz, s_W2p[64 + cc], v);
        g2a[k] = v;
    }
#pragma unroll
    for (int m = 0; m < 16; m++) {
        float hm = hl[m];
#pragma unroll
        for (int k = 0; k < 16; k++)
            g2a[k] = fmaf(hm, s_W2a[m * 32 + cc0 + k], g2a[k]);
    }
#pragma unroll
    for (int q = 0; q < 2; q++) {
        uint4 u;
        u.x = pack2(g2a[8 * q + 0], g2a[8 * q + 1]);
        u.y = pack2(g2a[8 * q + 2], g2a[8 * q + 3]);
        u.z = pack2(g2a[8 * q + 4], g2a[8 * q + 5]);
        u.w = pack2(g2a[8 * q + 6], g2a[8 * q + 7]);
        d_G2h[i * 4 + half * 2 + q] = u;
    }
}

// ---------------- K8: layer2 quad-per-node seg-max(fp16), BN+ReLU, pool -------
// 4 threads per node; thread q owns channels [q*8, q*8+8).
__global__ void __launch_bounds__(256) k_layer2pool(
    const float* __restrict__ pos,
    const float* __restrict__ W2,
    const float* __restrict__ bn2m, const float* __restrict__ bn2v,
    const float* __restrict__ bn2w, const float* __restrict__ bn2b)
{
    __shared__ float s_w2p[96];   // W2 rows 16..18
    __shared__ float s_a[32], s_b[32];
    __shared__ unsigned s_pool[NCLUS * 32];
    int t = threadIdx.x;
    if (t < 96) s_w2p[t] = W2[16 * 32 + t];
    if (t < 32) {
        float sc = bn2w[t] * rsqrtf(bn2v[t] + EPSBN);
        s_a[t] = sc;
        s_b[t] = bn2b[t] - bn2m[t] * sc;
    }
#pragma unroll
    for (int q = 0; q < 8; q++) s_pool[q * 256 + t] = 0u;
    __syncthreads();

    int gid = blockIdx.x * blockDim.x + t;   // 4*N threads
    int i = gid >> 2, q = gid & 3;
    unsigned start = d_offset[i], deg = d_count[i];
    const __half2 NEGINF2 = __floats2half2_rn(-65504.0f, -65504.0f);
    __half2 acc0 = NEGINF2, acc1 = NEGINF2, acc2 = NEGINF2, acc3 = NEGINF2;

#pragma unroll 4
    for (unsigned e = 0; e < deg; e++) {
        int s = d_sorted_src[start + e];
        uint4 u = d_G2h[s * 4 + q];
        acc0 = h2max(acc0, u.x); acc1 = h2max(acc1, u.y);
        acc2 = h2max(acc2, u.z); acc3 = h2max(acc3, u.w);
    }
    float accf[8];
    {
        float2 f0 = __half22float2(acc0), f1 = __half22float2(acc1);
        float2 f2 = __half22float2(acc2), f3 = __half22float2(acc3);
        accf[0] = f0.x; accf[1] = f0.y; accf[2] = f1.x; accf[3] = f1.y;
        accf[4] = f2.x; accf[5] = f2.y; accf[6] = f3.x; accf[7] = f3.y;
    }

    float px = pos[3 * i], py = pos[3 * i + 1], pz = pos[3 * i + 2];
    unsigned base = (unsigned)d_clus[i] * 32u;
    int c0 = q * 8;
#pragma unroll
    for (int j = 0; j < 8; j++) {
        int c = c0 + j;
        float dterm = px * s_w2p[c] + py * s_w2p[32 + c] + pz * s_w2p[64 + c];
        float agg = (deg == 0u) ? 0.0f : (accf[j] - dterm);
        float h2v = fmaxf(fmaf(agg, s_a[c], s_b[c]), 0.0f);   // >= 0
        atomicMax(&s_pool[base + c], __float_as_uint(h2v) | 0x80000000u);
    }
    __syncthreads();
#pragma unroll
    for (int qq = 0; qq < 8; qq++) {
        int j = qq * 256 + t;
        unsigned v = s_pool[j];
        if (v) atomicMax(&d_pool[j], v);
    }
}

// ---------------- K9: decode pooled -> output ---------------------------------
__global__ void k_out(float* __restrict__ out) {
    int t = blockIdx.x * blockDim.x + threadIdx.x;
    if (t < NCLUS * 32) {
        unsigned u = d_pool[t];
        out[t] = u ? __uint_as_float(u & 0x7FFFFFFFu) : 0.0f;
    }
}

// ---------------- host launch -------------------------------------------------
extern "C" void kernel_launch(void* const* d_in, const int* in_sizes, int n_in,
                              void* d_out, int out_size)
{
    const float* x    = (const float*)d_in[0];
    const float* pos  = (const float*)d_in[1];
    const void*  ei   = (const void*)d_in[2];
    const float* W1   = (const float*)d_in[3];
    const float* b1   = (const float*)d_in[4];
    const float* bn1m = (const float*)d_in[5];
    const float* bn1v = (const float*)d_in[6];
    const float* bn1w = (const float*)d_in[7];
    const float* bn1b = (const float*)d_in[8];
    const float* W2   = (const float*)d_in[9];
    const float* b2   = (const float*)d_in[10];
    const float* bn2m = (const float*)d_in[11];
    const float* bn2v = (const float*)d_in[12];
    const float* bn2w = (const float*)d_in[13];
    const float* bn2b = (const float*)d_in[14];
    float* out = (float*)d_out;

    k_zero<<<8, 256>>>(ei);
    k_init<<<N_NODES / 256, 256>>>(x, pos, W1, b1);
    k_hist<<<N_EDGES / 512, 256>>>(ei);
    k_scanA<<<256, 1024>>>();
    k_scanB<<<1, 256>>>();
    k_scanC<<<256, 1024>>>();
    k_scatter<<<N_EDGES / 512, 256>>>(ei);
    k_layer1<<<N_NODES * 2 / 256, 256>>>(pos, W1, bn1m, bn1v, bn1w, bn1b, W2, b2);
    k_layer2pool<<<N_NODES * 4 / 256, 256>>>(pos, W2, bn2m, bn2v, bn2w, bn2b);
    k_out<<<8, 256>>>(out);
}